// round 16
// baseline (speedup 1.0000x reference)
#include <cuda_runtime.h>
#include <math.h>

#define TWO_PI 6.283185307179586f
#define EPS 1e-6f
#define NEG_HALF_LOG2E (-0.7213475204444817f)

typedef unsigned long long u64;

// ---------------- device scratch ----------------
#define MAXM 120000
#define MAXS 4096
#define MAXROWS 320

__device__ float g_W[MAXM], g_PX[MAXM], g_PY[MAXM];
__device__ float g_EA[MAXM], g_EB[MAXM], g_EC[MAXM];
__device__ float g_C00[MAXM], g_C01[MAXM], g_C11[MAXM];
__device__ float g_part0[MAXM], g_part1[MAXM];

// selected mixtures, packed: g_S4[dst]=(w,px,py,c00), g_S2[dst]=(c01,c11)
__device__ float4 g_S4[MAXS];
__device__ float2 g_S2[MAXS];

__device__ float g_TOT[MAXROWS], g_SIG[MAXROWS];
__device__ int g_tick = 0;              // finale ticket; self-resetting

__device__ __forceinline__ float fast_exp2(float x) {
    float y; asm("ex2.approx.ftz.f32 %0, %1;" : "=f"(y) : "f"(x)); return y;
}
__device__ __forceinline__ float fast_sqrt(float x) {
    float y; asm("sqrt.approx.ftz.f32 %0, %1;" : "=f"(y) : "f"(x)); return y;
}
__device__ __forceinline__ float fast_rcp(float x) {
    float y; asm("rcp.approx.ftz.f32 %0, %1;" : "=f"(y) : "f"(x)); return y;
}

// ---- packed f32x2 helpers ----
__device__ __forceinline__ u64 pk2(float lo, float hi) {
    u64 r; asm("mov.b64 %0, {%1, %2};" : "=l"(r) : "f"(lo), "f"(hi)); return r;
}
__device__ __forceinline__ void upk2(u64 v, float& lo, float& hi) {
    asm("mov.b64 {%0, %1}, %2;" : "=f"(lo), "=f"(hi) : "l"(v));
}
__device__ __forceinline__ u64 add2(u64 a, u64 b) {
    u64 r; asm("add.rn.f32x2 %0, %1, %2;" : "=l"(r) : "l"(a), "l"(b)); return r;
}
__device__ __forceinline__ u64 mul2(u64 a, u64 b) {
    u64 r; asm("mul.rn.f32x2 %0, %1, %2;" : "=l"(r) : "l"(a), "l"(b)); return r;
}
__device__ __forceinline__ u64 fma2(u64 a, u64 b, u64 c) {
    u64 r; asm("fma.rn.f32x2 %0, %1, %2, %3;" : "=l"(r) : "l"(a), "l"(b), "l"(c)); return r;
}

// ---------------- conv with fused batchnorm prologue ----------------
// grid (ceil(Lo*N/256), B). Kernel table staged in smem (coalesced); for
// FIRST the in_x batch slice (448 floats) is staged too; data side for
// non-first layers is 2 vector loads from the packed selected arrays.
template<int Li, int Nd, int Lo, int Nk, int FIRST>
__global__ __launch_bounds__(256) void k_conv(
    const float* __restrict__ in_x, const float* __restrict__ kern)
{
    constexpr int N = Li * Nd * Nk;
    constexpr int perB = Lo * N;
    constexpr int KSZ = Lo * Li * Nk * 7;
    __shared__ float s_kern[KSZ];
    __shared__ float s_in[FIRST ? 448 : 8];
    __shared__ float s_scl[8];
    __shared__ float s_red[64];
    const int tid = threadIdx.x;
    const int b = blockIdx.y;

    // ---- stage kernel table (coalesced) ----
    for (int j = tid; j < KSZ; j += 256) s_kern[j] = kern[j];

    if (FIRST) {
        // stage in_x slice for this b (64 comps * 7)
        for (int j = tid; j < 448; j += 256) s_in[j] = in_x[b * 448 + j];
        __syncthreads();
        if (tid < 64) {
            const float* m = s_in + tid * 7;
            float det = m[3] * m[6] - m[4] * m[5];
            s_red[tid] = fabsf(m[0] * TWO_PI * fast_sqrt(fmaxf(det, EPS)));
        }
        __syncthreads();
        if (tid < 32) {
            float v = s_red[tid] + s_red[tid + 32];
            for (int o = 16; o > 0; o >>= 1) v += __shfl_xor_sync(0xffffffffu, v, o);
            if (tid == 0) s_scl[0] = 1.0f / (v + EPS);
        }
        __syncthreads();
    } else {
        if (tid < Li * 32) {
            int li = tid >> 5, bb = tid & 31;
            float v = g_TOT[bb * Li + li];
            for (int o = 16; o > 0; o >>= 1) v += __shfl_xor_sync(0xffffffffu, v, o);
            if ((tid & 31) == 0) s_scl[li] = 1.0f / (v * (1.0f / 32.0f) + EPS);
        }
        __syncthreads();
    }

    int i = blockIdx.x * 256 + tid;
    if (i >= perB) return;
    int nk = i % Nk; int t = i / Nk;
    int nd = t % Nd; t /= Nd;
    int li = t % Li; int lo = t / Li;

    float wd, pdx, pdy, d00, d01, d11;
    if (FIRST) {
        const float* m = s_in + (li * Nd + nd) * 7;
        wd = m[0] * s_scl[0]; pdx = m[1]; pdy = m[2];
        d00 = m[3]; d01 = m[4]; d11 = m[6];
    } else {
        int di = (b * Li + li) * Nd + nd;
        float4 a = g_S4[di];
        float2 c2 = g_S2[di];
        wd = a.x * s_scl[li]; pdx = a.y; pdy = a.z;
        d00 = a.w; d01 = c2.x; d11 = c2.y;
    }

    const float* kp = s_kern + ((lo * Li + li) * Nk + nk) * 7;
    float wk = kp[0], pkx = kp[1], pky = kp[2];
    float k00 = kp[3], k01 = kp[4], k11 = kp[6];

    float s00 = d00 + k00, s01 = d01 + k01, s11 = d11 + k11;
    float dd = d00 * d11 - d01 * d01;
    float dk = k00 * k11 - k01 * k01;
    float ds = s00 * s11 - s01 * s01;
    float inv = fast_rcp(fmaxf(ds, EPS));
    float ws = wd * wk * TWO_PI * fast_sqrt(dd * dk * inv);

    int o = (b * Lo + lo) * N + (li * Nd + nd) * Nk + nk;
    g_W[o] = ws;
    g_PX[o] = pdx + pkx; g_PY[o] = pdy + pky;
    g_C00[o] = s00; g_C01[o] = s01; g_C11[o] = s11;
    g_EA[o] = NEG_HALF_LOG2E * s11 * inv;
    g_EB[o] = -NEG_HALF_LOG2E * (s01 + s01) * inv;
    g_EC[o] = NEG_HALF_LOG2E * s00 * inv;
}

// ---------------- eval: n-split (R15 verbatim) ----------------
template<int N, int SLICE, int Lo>
__global__ __launch_bounds__(128) void k_eval(const float* __restrict__ bias)
{
    constexpr int HALFS = (SLICE + 1) >> 1;
    __shared__ __align__(16) float4 sA[HALFS];
    __shared__ __align__(16) float4 sB[HALFS];
    __shared__ __align__(16) float4 sC[HALFS];

    const int tid = threadIdx.x;
    const int row = blockIdx.y >> 1;
    const int sp = blockIdx.y & 1;
    const int base = row * N;
    const int n0 = sp * SLICE;

    for (int u = tid; u < HALFS; u += 128) {
        int nA = n0 + 2 * u;
        float4 a, bq, c;
        if (nA < N) {
            int g = base + nA;
            a.x = g_PX[g]; a.z = g_PY[g];
            bq.x = g_EA[g]; bq.z = g_EB[g];
            c.x = g_EC[g]; c.z = g_W[g];
            if (nA + 1 < N) {
                a.y = g_PX[g + 1]; a.w = g_PY[g + 1];
                bq.y = g_EA[g + 1]; bq.w = g_EB[g + 1];
                c.y = g_EC[g + 1]; c.w = g_W[g + 1];
            } else {
                a.y = 0.0f; a.w = 0.0f; bq.y = 0.0f; bq.w = 0.0f;
                c.y = 0.0f; c.w = 0.0f;
            }
        } else {
            a = make_float4(0, 0, 0, 0); bq = a; c = a;
        }
        sA[u] = a; sB[u] = bq; sC[u] = c;
    }
    __syncthreads();

    const int k = blockIdx.x * 128 + tid;
    if (k >= N) return;

    float kx = g_PX[base + k], ky = g_PY[base + k];
    u64 nkx2 = pk2(-kx, -kx);
    u64 nky2 = pk2(-ky, -ky);
    u64 acc = 0ull;

    #pragma unroll 4
    for (int j = 0; j < HALFS; j++) {
        float4 a = sA[j];
        float4 bq = sB[j];
        float4 c = sC[j];
        u64 px2 = *(const u64*)&a.x;  u64 py2 = *(const u64*)&a.z;
        u64 ea2 = *(const u64*)&bq.x; u64 eb2 = *(const u64*)&bq.z;
        u64 ec2 = *(const u64*)&c.x;  u64 w2p = *(const u64*)&c.z;

        u64 dx = add2(px2, nkx2);
        u64 dy = add2(py2, nky2);
        u64 u  = fma2(ea2, dx, mul2(eb2, dy));
        u64 md = fma2(dx, u, mul2(mul2(ec2, dy), dy));
        float m0, m1; upk2(md, m0, m1);
        u64 e = pk2(fast_exp2(m0), fast_exp2(m1));
        acc = fma2(w2p, e, acc);
    }

    float a0, a1; upk2(acc, a0, a1);
    float p = a0 + a1;
    if (sp == 0) g_part0[base + k] = p;
    else         g_part1[base + k] = p;
}

// ---------------- two-level rank top-k with fused partial-combine ----------------
template<int N, int NCH, int Lo, int NSEL, int DOF>
__global__ __launch_bounds__(32 * NCH) void k_topk(
    int rows, const float* __restrict__ bias, float* __restrict__ out)
{
    constexpr int NC = NCH * 64;
    const int tid = threadIdx.x;
    const int row = blockIdx.x;
    const int base = row * N;

    __shared__ __align__(16) u64 keys[NC];
    __shared__ float sW2[NC];
    __shared__ __align__(16) u64 sCand[NCH * NSEL + 2];
    __shared__ int s_cnt;
    __shared__ float s_out[64];
    __shared__ int s_last;
    __shared__ float scl[10];
    __shared__ float logit[320];

    if (tid == 0) s_cnt = 0;
    const float bs = bias[row % Lo];
    for (int n = tid; n < NC; n += 32 * NCH) {
        if (n < N) {
            float v = g_part0[base + n] + g_part1[base + n] + bs;
            float scale = fmaxf(v, 0.0f) * fast_rcp(fabsf(v) + EPS);
            float w2 = g_W[base + n] * scale;
            sW2[n] = w2;
            keys[n] = ((u64)__float_as_uint(fabsf(w2)) << 32) | (u64)(unsigned)(~(unsigned)n);
        } else {
            keys[n] = 0ull;
        }
    }
    __syncthreads();

    // level 1: per-warp chunk rank
    {
        int w = tid >> 5, lane = tid & 31;
        int kb = w << 6;
        u64 k0 = keys[kb + lane];
        u64 k1 = keys[kb + lane + 32];
        int r0 = 0, r1 = 0;
        const ulonglong2* Q = (const ulonglong2*)(keys + kb);
        #pragma unroll 8
        for (int j = 0; j < 32; j++) {
            ulonglong2 q = Q[j];
            r0 += (int)(q.x > k0) + (int)(q.y > k0);
            r1 += (int)(q.x > k1) + (int)(q.y > k1);
        }
        if (kb + lane < N && r0 < NSEL)      { int s = atomicAdd(&s_cnt, 1); sCand[s] = k0; }
        if (kb + lane + 32 < N && r1 < NSEL) { int s = atomicAdd(&s_cnt, 1); sCand[s] = k1; }
    }
    __syncthreads();
    int m = s_cnt;
    if (tid == 0 && (m & 1)) sCand[m] = 0ull;
    __syncthreads();

    // level 2: exact rank among candidates + packed gather
    {
        int mq = (m + 1) >> 1;
        const ulonglong2* Q = (const ulonglong2*)sCand;
        for (int i = tid; i < m; i += 32 * NCH) {
            u64 mykey = sCand[i];
            int rank = 0;
            #pragma unroll 4
            for (int j = 0; j < mq; j++) {
                ulonglong2 q = Q[j];
                rank += (int)(q.x > mykey) + (int)(q.y > mykey);
            }
            if (rank < NSEL) {
                int n = (int)(~(unsigned)mykey);
                int src = base + n;
                int dst = row * NSEL + rank;
                float wv = sW2[n];
                float c00 = g_C00[src], c01 = g_C01[src], c11 = g_C11[src];
                g_S4[dst] = make_float4(wv, g_PX[src], g_PY[src], c00);
                g_S2[dst] = make_float2(c01, c11);
                float I = wv * TWO_PI * fast_sqrt(fmaxf(c00 * c11 - c01 * c01, EPS));
                s_out[rank] = fabsf(I);
                s_out[32 + rank] = I;
            }
        }
    }
    __syncthreads();
    if (tid == 0) {
        float tot = 0.0f, sg = 0.0f;
        #pragma unroll
        for (int t = 0; t < NSEL; t++) { tot += s_out[t]; sg += s_out[32 + t]; }
        g_TOT[row] = tot;
        if (DOF) g_SIG[row] = sg;
    }

    if (!DOF) return;

    // fused finale
    if (tid == 0) {
        __threadfence();
        int t = atomicAdd(&g_tick, 1);
        s_last = (t == rows - 1) ? 1 : 0;
        if (s_last) g_tick = 0;
    }
    __syncthreads();
    if (!s_last) return;
    __threadfence();

    if (tid < 10) {
        float t = 0.0f;
        for (int b = 0; b < 32; b++) t += g_TOT[b * 10 + tid];
        scl[tid] = 1.0f / (t / 32.0f + EPS);
    }
    __syncthreads();
    for (int i = tid; i < 320; i += 32 * NCH) logit[i] = g_SIG[i] * scl[i % 10];
    __syncthreads();
    if (tid < 32) {
        int b = tid;
        float mx = -INFINITY;
        for (int l = 0; l < 10; l++) mx = fmaxf(mx, logit[b * 10 + l]);
        float se = 0.0f;
        for (int l = 0; l < 10; l++) se += expf(logit[b * 10 + l] - mx);
        float lse = mx + logf(se);
        for (int l = 0; l < 10; l++) out[b * 10 + l] = logit[b * 10 + l] - lse;
    }
}

extern "C" void kernel_launch(void* const* d_in, const int* in_sizes, int n_in,
                              void* d_out, int out_size) {
    const float* in_x = (const float*)d_in[0];
    const float* k1 = (const float*)d_in[1];
    const float* k2 = (const float*)d_in[2];
    const float* k3 = (const float*)d_in[3];
    const float* b1 = (const float*)d_in[4];
    const float* b2 = (const float*)d_in[5];
    const float* b3 = (const float*)d_in[6];
    float* out = (float*)d_out;

    // ===== layer 1: Li=1, Nd=64, Lo=5, Nk=5 -> N=320, rows=160, nsel=25 =====
    k_conv<1, 64, 5, 5, 1><<<dim3(7, 32), 256>>>(in_x, k1);
    k_eval<320, 160, 5><<<dim3(3, 320), 128>>>(b1);
    k_topk<320, 5, 5, 25, 0><<<160, 160>>>(160, b1, out);

    // ===== layer 2: Li=5, Nd=25, Lo=6, Nk=5 -> N=625, rows=192, nsel=12 =====
    k_conv<5, 25, 6, 5, 0><<<dim3(15, 32), 256>>>(in_x, k2);
    k_eval<625, 314, 6><<<dim3(5, 384), 128>>>(b2);
    k_topk<625, 10, 6, 12, 0><<<192, 320>>>(192, b2, out);

    // ===== layer 3: Li=6, Nd=12, Lo=10, Nk=5 -> N=360, rows=320, nsel=5 =====
    k_conv<6, 12, 10, 5, 0><<<dim3(15, 32), 256>>>(in_x, k3);
    k_eval<360, 180, 10><<<dim3(3, 640), 128>>>(b3);
    k_topk<360, 6, 10, 5, 1><<<320, 192>>>(320, b3, out);
}

// round 17
// speedup vs baseline: 1.0425x; 1.0425x over previous
#include <cuda_runtime.h>
#include <math.h>

#define TWO_PI 6.283185307179586f
#define EPS 1e-6f
#define NEG_HALF_LOG2E (-0.7213475204444817f)

typedef unsigned long long u64;

// ---------------- device scratch ----------------
#define MAXM 120000
#define MAXS 4096
#define MAXROWS 320

__device__ float g_W[MAXM], g_PX[MAXM], g_PY[MAXM];
__device__ float g_EA[MAXM], g_EB[MAXM], g_EC[MAXM];
__device__ float g_C00[MAXM], g_C01[MAXM], g_C11[MAXM];
__device__ float g_part0[MAXM], g_part1[MAXM];

__device__ float g_SW[MAXS], g_SPX[MAXS], g_SPY[MAXS];
__device__ float g_SC00[MAXS], g_SC01[MAXS], g_SC11[MAXS];

__device__ float g_TOT[MAXROWS], g_SIG[MAXROWS];
__device__ int g_tick = 0;              // finale ticket; self-resetting

__device__ __forceinline__ float fast_exp2(float x) {
    float y; asm("ex2.approx.ftz.f32 %0, %1;" : "=f"(y) : "f"(x)); return y;
}
__device__ __forceinline__ float fast_sqrt(float x) {
    float y; asm("sqrt.approx.ftz.f32 %0, %1;" : "=f"(y) : "f"(x)); return y;
}
__device__ __forceinline__ float fast_rcp(float x) {
    float y; asm("rcp.approx.ftz.f32 %0, %1;" : "=f"(y) : "f"(x)); return y;
}

// ---- packed f32x2 helpers ----
__device__ __forceinline__ u64 pk2(float lo, float hi) {
    u64 r; asm("mov.b64 %0, {%1, %2};" : "=l"(r) : "f"(lo), "f"(hi)); return r;
}
__device__ __forceinline__ void upk2(u64 v, float& lo, float& hi) {
    asm("mov.b64 {%0, %1}, %2;" : "=f"(lo), "=f"(hi) : "l"(v));
}
__device__ __forceinline__ u64 add2(u64 a, u64 b) {
    u64 r; asm("add.rn.f32x2 %0, %1, %2;" : "=l"(r) : "l"(a), "l"(b)); return r;
}
__device__ __forceinline__ u64 mul2(u64 a, u64 b) {
    u64 r; asm("mul.rn.f32x2 %0, %1, %2;" : "=l"(r) : "l"(a), "l"(b)); return r;
}
__device__ __forceinline__ u64 fma2(u64 a, u64 b, u64 c) {
    u64 r; asm("fma.rn.f32x2 %0, %1, %2, %3;" : "=l"(r) : "l"(a), "l"(b), "l"(c)); return r;
}

// ---------------- conv with fused batchnorm prologue (R15 verbatim) ----------------
template<int Li, int Nd, int Lo, int Nk, int FIRST>
__global__ __launch_bounds__(256) void k_conv(
    const float* __restrict__ in_x, const float* __restrict__ kern)
{
    constexpr int N = Li * Nd * Nk;
    constexpr int perB = Lo * N;
    __shared__ float s_scl[8];
    __shared__ float s_red[64];
    const int tid = threadIdx.x;
    const int b = blockIdx.y;

    if (FIRST) {
        if (tid < 64) {
            const float* m = in_x + (b * 64 + tid) * 7;
            float det = m[3] * m[6] - m[4] * m[5];
            s_red[tid] = fabsf(m[0] * TWO_PI * fast_sqrt(fmaxf(det, EPS)));
        }
        __syncthreads();
        if (tid < 32) {
            float v = s_red[tid] + s_red[tid + 32];
            for (int o = 16; o > 0; o >>= 1) v += __shfl_xor_sync(0xffffffffu, v, o);
            if (tid == 0) s_scl[0] = 1.0f / (v + EPS);
        }
        __syncthreads();
    } else {
        if (tid < Li * 32) {
            int li = tid >> 5, bb = tid & 31;
            float v = g_TOT[bb * Li + li];
            for (int o = 16; o > 0; o >>= 1) v += __shfl_xor_sync(0xffffffffu, v, o);
            if ((tid & 31) == 0) s_scl[li] = 1.0f / (v * (1.0f / 32.0f) + EPS);
        }
        __syncthreads();
    }

    int i = blockIdx.x * 256 + tid;
    if (i >= perB) return;
    int nk = i % Nk; int t = i / Nk;
    int nd = t % Nd; t /= Nd;
    int li = t % Li; int lo = t / Li;

    int di = (b * Li + li) * Nd + nd;
    float wd, pdx, pdy, d00, d01, d11;
    if (FIRST) {
        const float* m = in_x + di * 7;
        wd = m[0] * s_scl[0]; pdx = m[1]; pdy = m[2];
        d00 = m[3]; d01 = m[4]; d11 = m[6];
    } else {
        wd = g_SW[di] * s_scl[li];
        pdx = g_SPX[di]; pdy = g_SPY[di];
        d00 = g_SC00[di]; d01 = g_SC01[di]; d11 = g_SC11[di];
    }

    const float* kp = kern + (((lo * Li + li) * Nk) + nk) * 7;
    float wk = kp[0], pkx = kp[1], pky = kp[2];
    float k00 = kp[3], k01 = kp[4], k11 = kp[6];

    float s00 = d00 + k00, s01 = d01 + k01, s11 = d11 + k11;
    float dd = d00 * d11 - d01 * d01;
    float dk = k00 * k11 - k01 * k01;
    float ds = s00 * s11 - s01 * s01;
    float inv = fast_rcp(fmaxf(ds, EPS));
    float ws = wd * wk * TWO_PI * fast_sqrt(dd * dk * inv);

    int o = (b * Lo + lo) * N + (li * Nd + nd) * Nk + nk;
    g_W[o] = ws;
    g_PX[o] = pdx + pkx; g_PY[o] = pdy + pky;
    g_C00[o] = s00; g_C01[o] = s01; g_C11[o] = s11;
    g_EA[o] = NEG_HALF_LOG2E * s11 * inv;
    g_EB[o] = -NEG_HALF_LOG2E * (s01 + s01) * inv;
    g_EC[o] = NEG_HALF_LOG2E * s00 * inv;
}

// ---------------- eval: n-split (R15), register-capped for 16 blocks/SM ----------------
template<int N, int SLICE, int Lo>
__global__ __launch_bounds__(128, 16) void k_eval(const float* __restrict__ bias)
{
    constexpr int HALFS = (SLICE + 1) >> 1;
    __shared__ __align__(16) float4 sA[HALFS];
    __shared__ __align__(16) float4 sB[HALFS];
    __shared__ __align__(16) float4 sC[HALFS];

    const int tid = threadIdx.x;
    const int row = blockIdx.y >> 1;
    const int sp = blockIdx.y & 1;
    const int base = row * N;
    const int n0 = sp * SLICE;

    for (int u = tid; u < HALFS; u += 128) {
        int nA = n0 + 2 * u;
        float4 a, bq, c;
        if (nA < N) {
            int g = base + nA;
            a.x = g_PX[g]; a.z = g_PY[g];
            bq.x = g_EA[g]; bq.z = g_EB[g];
            c.x = g_EC[g]; c.z = g_W[g];
            if (nA + 1 < N) {
                a.y = g_PX[g + 1]; a.w = g_PY[g + 1];
                bq.y = g_EA[g + 1]; bq.w = g_EB[g + 1];
                c.y = g_EC[g + 1]; c.w = g_W[g + 1];
            } else {
                a.y = 0.0f; a.w = 0.0f; bq.y = 0.0f; bq.w = 0.0f;
                c.y = 0.0f; c.w = 0.0f;
            }
        } else {
            a = make_float4(0, 0, 0, 0); bq = a; c = a;
        }
        sA[u] = a; sB[u] = bq; sC[u] = c;
    }
    __syncthreads();

    const int k = blockIdx.x * 128 + tid;
    if (k >= N) return;

    float kx = g_PX[base + k], ky = g_PY[base + k];
    u64 nkx2 = pk2(-kx, -kx);
    u64 nky2 = pk2(-ky, -ky);
    u64 acc = 0ull;

    #pragma unroll 4
    for (int j = 0; j < HALFS; j++) {
        float4 a = sA[j];
        float4 bq = sB[j];
        float4 c = sC[j];
        u64 px2 = *(const u64*)&a.x;  u64 py2 = *(const u64*)&a.z;
        u64 ea2 = *(const u64*)&bq.x; u64 eb2 = *(const u64*)&bq.z;
        u64 ec2 = *(const u64*)&c.x;  u64 w2p = *(const u64*)&c.z;

        u64 dx = add2(px2, nkx2);
        u64 dy = add2(py2, nky2);
        u64 u  = fma2(ea2, dx, mul2(eb2, dy));
        u64 md = fma2(dx, u, mul2(mul2(ec2, dy), dy));
        float m0, m1; upk2(md, m0, m1);
        u64 e = pk2(fast_exp2(m0), fast_exp2(m1));
        acc = fma2(w2p, e, acc);
    }

    float a0, a1; upk2(acc, a0, a1);
    float p = a0 + a1;
    if (sp == 0) g_part0[base + k] = p;
    else         g_part1[base + k] = p;
}

// ---------------- two-level rank top-k with fused partial-combine (R15 verbatim) ----------------
template<int N, int NCH, int Lo, int NSEL, int DOF>
__global__ __launch_bounds__(32 * NCH) void k_topk(
    int rows, const float* __restrict__ bias, float* __restrict__ out)
{
    constexpr int NC = NCH * 64;
    const int tid = threadIdx.x;
    const int row = blockIdx.x;
    const int base = row * N;

    __shared__ __align__(16) u64 keys[NC];
    __shared__ float sW2[NC];
    __shared__ __align__(16) u64 sCand[NCH * NSEL + 2];
    __shared__ int s_cnt;
    __shared__ float s_out[64];
    __shared__ int s_last;
    __shared__ float scl[10];
    __shared__ float logit[320];

    if (tid == 0) s_cnt = 0;
    const float bs = bias[row % Lo];
    for (int n = tid; n < NC; n += 32 * NCH) {
        if (n < N) {
            float v = g_part0[base + n] + g_part1[base + n] + bs;
            float scale = fmaxf(v, 0.0f) * fast_rcp(fabsf(v) + EPS);
            float w2 = g_W[base + n] * scale;
            sW2[n] = w2;
            keys[n] = ((u64)__float_as_uint(fabsf(w2)) << 32) | (u64)(unsigned)(~(unsigned)n);
        } else {
            keys[n] = 0ull;
        }
    }
    __syncthreads();

    // level 1: per-warp chunk rank
    {
        int w = tid >> 5, lane = tid & 31;
        int kb = w << 6;
        u64 k0 = keys[kb + lane];
        u64 k1 = keys[kb + lane + 32];
        int r0 = 0, r1 = 0;
        const ulonglong2* Q = (const ulonglong2*)(keys + kb);
        #pragma unroll 8
        for (int j = 0; j < 32; j++) {
            ulonglong2 q = Q[j];
            r0 += (int)(q.x > k0) + (int)(q.y > k0);
            r1 += (int)(q.x > k1) + (int)(q.y > k1);
        }
        if (kb + lane < N && r0 < NSEL)      { int s = atomicAdd(&s_cnt, 1); sCand[s] = k0; }
        if (kb + lane + 32 < N && r1 < NSEL) { int s = atomicAdd(&s_cnt, 1); sCand[s] = k1; }
    }
    __syncthreads();
    int m = s_cnt;
    if (tid == 0 && (m & 1)) sCand[m] = 0ull;
    __syncthreads();

    // level 2: exact rank among candidates + gather
    {
        int mq = (m + 1) >> 1;
        const ulonglong2* Q = (const ulonglong2*)sCand;
        for (int i = tid; i < m; i += 32 * NCH) {
            u64 mykey = sCand[i];
            int rank = 0;
            #pragma unroll 4
            for (int j = 0; j < mq; j++) {
                ulonglong2 q = Q[j];
                rank += (int)(q.x > mykey) + (int)(q.y > mykey);
            }
            if (rank < NSEL) {
                int n = (int)(~(unsigned)mykey);
                int src = base + n;
                int dst = row * NSEL + rank;
                float wv = sW2[n];
                float c00 = g_C00[src], c01 = g_C01[src], c11 = g_C11[src];
                g_SW[dst] = wv;
                g_SPX[dst] = g_PX[src]; g_SPY[dst] = g_PY[src];
                g_SC00[dst] = c00; g_SC01[dst] = c01; g_SC11[dst] = c11;
                float I = wv * TWO_PI * fast_sqrt(fmaxf(c00 * c11 - c01 * c01, EPS));
                s_out[rank] = fabsf(I);
                s_out[32 + rank] = I;
            }
        }
    }
    __syncthreads();
    if (tid == 0) {
        float tot = 0.0f, sg = 0.0f;
        #pragma unroll
        for (int t = 0; t < NSEL; t++) { tot += s_out[t]; sg += s_out[32 + t]; }
        g_TOT[row] = tot;
        if (DOF) g_SIG[row] = sg;
    }

    if (!DOF) return;

    // fused finale
    if (tid == 0) {
        __threadfence();
        int t = atomicAdd(&g_tick, 1);
        s_last = (t == rows - 1) ? 1 : 0;
        if (s_last) g_tick = 0;
    }
    __syncthreads();
    if (!s_last) return;
    __threadfence();

    if (tid < 10) {
        float t = 0.0f;
        for (int b = 0; b < 32; b++) t += g_TOT[b * 10 + tid];
        scl[tid] = 1.0f / (t / 32.0f + EPS);
    }
    __syncthreads();
    for (int i = tid; i < 320; i += 32 * NCH) logit[i] = g_SIG[i] * scl[i % 10];
    __syncthreads();
    if (tid < 32) {
        int b = tid;
        float mx = -INFINITY;
        for (int l = 0; l < 10; l++) mx = fmaxf(mx, logit[b * 10 + l]);
        float se = 0.0f;
        for (int l = 0; l < 10; l++) se += expf(logit[b * 10 + l] - mx);
        float lse = mx + logf(se);
        for (int l = 0; l < 10; l++) out[b * 10 + l] = logit[b * 10 + l] - lse;
    }
}

extern "C" void kernel_launch(void* const* d_in, const int* in_sizes, int n_in,
                              void* d_out, int out_size) {
    const float* in_x = (const float*)d_in[0];
    const float* k1 = (const float*)d_in[1];
    const float* k2 = (const float*)d_in[2];
    const float* k3 = (const float*)d_in[3];
    const float* b1 = (const float*)d_in[4];
    const float* b2 = (const float*)d_in[5];
    const float* b3 = (const float*)d_in[6];
    float* out = (float*)d_out;

    // ===== layer 1: Li=1, Nd=64, Lo=5, Nk=5 -> N=320, rows=160, nsel=25 =====
    k_conv<1, 64, 5, 5, 1><<<dim3(7, 32), 256>>>(in_x, k1);
    k_eval<320, 160, 5><<<dim3(3, 320), 128>>>(b1);
    k_topk<320, 5, 5, 25, 0><<<160, 160>>>(160, b1, out);

    // ===== layer 2: Li=5, Nd=25, Lo=6, Nk=5 -> N=625, rows=192, nsel=12 =====
    k_conv<5, 25, 6, 5, 0><<<dim3(15, 32), 256>>>(in_x, k2);
    k_eval<625, 314, 6><<<dim3(5, 384), 128>>>(b2);
    k_topk<625, 10, 6, 12, 0><<<192, 320>>>(192, b2, out);

    // ===== layer 3: Li=6, Nd=12, Lo=10, Nk=5 -> N=360, rows=320, nsel=5 =====
    k_conv<6, 12, 10, 5, 0><<<dim3(15, 32), 256>>>(in_x, k3);
    k_eval<360, 180, 10><<<dim3(3, 640), 128>>>(b3);
    k_topk<360, 6, 10, 5, 1><<<320, 192>>>(320, b3, out);
}